// round 12
// baseline (speedup 1.0000x reference)
#include <cuda_runtime.h>
#include <cstdint>

// CustomRNN: h_t = W2 h_{t-1} + x_t w1 ; y_t = W3 h_t
// => causal conv y[b,t] = sum_k u_k x[b,t-k], u_k = W3 W2^k w1, KC=24.
// 4 graph-captured launches:
//  K1: P2=W2^2        | v0=w1, v1=W2 w1
//  K2: P4=P2^2        | v2,v3 = P2{v0,v1}
//  K3: v4..7=P4{v0..3} | v8..15=P4^2 v_b (2-3 block-local hops) | Y=W3*P4^2
//  K4: conv; prologue computes taps u_k from {W3,Y} x {v0..15}

#define BB   64
#define TT   8192
#define HH   256
#define OUTD 10
#define KC   24
#define TBc  1024
#define GP   260

typedef unsigned long long ull;

// ---- device scratch ----
__device__ __align__(16) float g_P2[HH * HH];
__device__ __align__(16) float g_P4[HH * HH];
__device__ __align__(16) float g_V[16][HH];     // v0..v15
__device__ __align__(16) float g_Y[OUTD * HH];  // Y = W3 * W2^8

// ---- packed f32x2 helpers ----
__device__ __forceinline__ ull fma2(ull a, ull b, ull c) {
    ull d;
    asm("fma.rn.f32x2 %0, %1, %2, %3;" : "=l"(d) : "l"(a), "l"(b), "l"(c));
    return d;
}
__device__ __forceinline__ ull pack_dup(float x) {
    ull d; unsigned u = __float_as_uint(x);
    asm("mov.b64 %0, {%1, %1};" : "=l"(d) : "r"(u));
    return d;
}
__device__ __forceinline__ float2 unpack2(ull a) {
    float2 f;
    asm("mov.b64 {%0, %1}, %2;" : "=f"(f.x), "=f"(f.y) : "l"(a));
    return f;
}

// ---- 32x32-tile GEMM square: C = X @ X (blocks 0..63) ----
__device__ void gemm_tile(const float* __restrict__ X, float* C, int bid,
                          float* sm)
{
    float* Xr = sm;                // [32][GP]
    float* Xc = sm + 32 * GP;      // [256][32]
    const int tid = threadIdx.x;
    const int i0 = (bid >> 3) * 32;
    const int j0 = (bid & 7) * 32;

    for (int n = tid; n < 32 * 256; n += 256) {
        int rr = n >> 8, kk = n & 255;
        Xr[rr * GP + kk] = __ldg(X + (i0 + rr) * HH + kk);
    }
    for (int n = tid; n < 256 * 32; n += 256) {
        int kk = n >> 5, jj = n & 31;
        Xc[kk * 32 + jj] = __ldg(X + kk * HH + j0 + jj);
    }
    __syncthreads();

    const int r0 = (tid >> 4) * 2;
    const int c0 = (tid & 15) * 2;
    ull q0 = 0ull, q1 = 0ull;
#pragma unroll 8
    for (int k = 0; k < 256; ++k) {
        ull cp = *reinterpret_cast<const ull*>(&Xc[k * 32 + c0]);
        ull a0 = pack_dup(Xr[r0 * GP + k]);
        ull a1 = pack_dup(Xr[(r0 + 1) * GP + k]);
        q0 = fma2(a0, cp, q0);
        q1 = fma2(a1, cp, q1);
    }
    float2 f0 = unpack2(q0), f1 = unpack2(q1);
    *reinterpret_cast<float2*>(&C[(i0 + r0) * HH + j0 + c0]) = f0;
    *reinterpret_cast<float2*>(&C[(i0 + r0 + 1) * HH + j0 + c0]) = f1;
}

// ---- 32-row matvec slice with prefetch: vout[row0..row0+31] = M @ vin ----
__device__ void matvec32(const float* __restrict__ M,
                         const float* __restrict__ vin,
                         float* __restrict__ vout, int row0)
{
    const int w = threadIdx.x >> 5, l = threadIdx.x & 31;
    const float4* vp = reinterpret_cast<const float4*>(vin);
    float4 va = __ldg(vp + l);
    float4 vb = __ldg(vp + 32 + l);
    float4 ma[4], mb[4];
#pragma unroll
    for (int rr = 0; rr < 4; ++rr) {
        const float4* mp =
            reinterpret_cast<const float4*>(M + (row0 + w + rr * 8) * HH);
        ma[rr] = __ldg(mp + l);
        mb[rr] = __ldg(mp + 32 + l);
    }
    float p[4];
#pragma unroll
    for (int rr = 0; rr < 4; ++rr)
        p[rr] = ma[rr].x * va.x + ma[rr].y * va.y + ma[rr].z * va.z + ma[rr].w * va.w
              + mb[rr].x * vb.x + mb[rr].y * vb.y + mb[rr].z * vb.z + mb[rr].w * vb.w;
#pragma unroll
    for (int off = 16; off; off >>= 1)
#pragma unroll
        for (int rr = 0; rr < 4; ++rr)
            p[rr] += __shfl_xor_sync(0xffffffffu, p[rr], off);
    if (l == 0) {
#pragma unroll
        for (int rr = 0; rr < 4; ++rr) vout[row0 + w + rr * 8] = p[rr];
    }
}

// ---- block-local chained matvec: vdst = M^hops @ vsrc (one block) ----
__device__ void chain_matvec(const float* __restrict__ M,
                             const float* __restrict__ vsrc,
                             float* __restrict__ vdst, int hops)
{
    __shared__ float buf[2][HH];
    const int tid = threadIdx.x, w = tid >> 5, l = tid & 31;
    buf[0][tid] = __ldg(vsrc + tid);
    __syncthreads();
    int cur = 0;
    for (int h = 0; h < hops; ++h) {
        const float4* v4 = reinterpret_cast<const float4*>(buf[cur]);
        float4 va = v4[l], vb = v4[32 + l];
        float* outp = (h == hops - 1) ? vdst : buf[cur ^ 1];
        for (int ib = 0; ib < 8; ++ib) {
            float4 ma[4], mb[4];
#pragma unroll
            for (int rr = 0; rr < 4; ++rr) {
                const float4* mp = reinterpret_cast<const float4*>(
                    M + (w * 32 + ib * 4 + rr) * HH);
                ma[rr] = __ldg(mp + l);
                mb[rr] = __ldg(mp + 32 + l);
            }
            float p[4];
#pragma unroll
            for (int rr = 0; rr < 4; ++rr)
                p[rr] = ma[rr].x * va.x + ma[rr].y * va.y + ma[rr].z * va.z + ma[rr].w * va.w
                      + mb[rr].x * vb.x + mb[rr].y * vb.y + mb[rr].z * vb.z + mb[rr].w * vb.w;
#pragma unroll
            for (int off = 16; off; off >>= 1)
#pragma unroll
                for (int rr = 0; rr < 4; ++rr)
                    p[rr] += __shfl_xor_sync(0xffffffffu, p[rr], off);
            if (l == 0) {
#pragma unroll
                for (int rr = 0; rr < 4; ++rr) outp[w * 32 + ib * 4 + rr] = p[rr];
            }
        }
        __syncthreads();
        cur ^= 1;
    }
}

// ---- Y row: g_Y[o] = W3[o] @ P4 @ P4 (two in-block vec-mat passes) ----
__device__ void y_row(const float* __restrict__ W3, int o)
{
    __shared__ float r0[HH], r1[HH];
    const int tid = threadIdx.x;
    r0[tid] = __ldg(W3 + o * HH + tid);
    __syncthreads();
    float acc = 0.f;
#pragma unroll 8
    for (int k = 0; k < HH; ++k)
        acc = fmaf(r0[k], __ldg(g_P4 + k * HH + tid), acc);
    r1[tid] = acc;
    __syncthreads();
    acc = 0.f;
#pragma unroll 8
    for (int k = 0; k < HH; ++k)
        acc = fmaf(r1[k], __ldg(g_P4 + k * HH + tid), acc);
    g_Y[o * HH + tid] = acc;
}

// ---- K1/K2: GEMM square + seed matvecs ----
#define GEMM_SMEM_BYTES ((32 * GP + 256 * 32) * 4)

extern "C" __global__ void __launch_bounds__(256, 2)
gemm_seed_kernel(const float* __restrict__ W2,
                 const float* __restrict__ W1, int phase)
{
    extern __shared__ float sm[];
    const int bid = blockIdx.x;
    const float* X = (phase == 0) ? W2 : g_P2;
    float*       C = (phase == 0) ? g_P2 : g_P4;

    if (bid < 64) {
        gemm_tile(X, C, bid, sm);
    } else if (phase == 0) {
        if (bid == 64) g_V[0][threadIdx.x] = __ldg(W1 + threadIdx.x);
        matvec32(W2, W1, &g_V[1][0], (bid - 64) * 32);
    } else {
        int s = (bid - 64) >> 3;
        matvec32(g_P2, &g_V[s][0], &g_V[2 + s][0], ((bid - 64) & 7) * 32);
    }
}

// ---- K3: v4..7 slices | v8..15 chained | Y rows  (grid 50) ----
extern "C" __global__ void __launch_bounds__(256)
prep_kernel(const float* __restrict__ W3)
{
    const int bid = blockIdx.x;
    if (bid < 32) {
        int s = bid >> 3;
        matvec32(g_P4, &g_V[s][0], &g_V[4 + s][0], (bid & 7) * 32);
    } else if (bid < 40) {
        int j = bid - 32;                 // v_{8+j} = P4^2 v_j
        int hops = (j < 4) ? 2 : 3;       // j>=4: P4^3 v_{j-4}
        int src  = (j < 4) ? j : j - 4;
        chain_matvec(g_P4, &g_V[src][0], &g_V[8 + j][0], hops);
    } else {
        y_row(W3, bid - 40);
    }
}

// ---- K4: conv. grid (8, 64) x 256 threads, 4 t/thread, tap prologue ----
extern "C" __global__ void __launch_bounds__(256)
conv_kernel(const float* __restrict__ x, float* __restrict__ y,
            const float* __restrict__ W3)
{
    __shared__ __align__(16) float xs[TBc + KC];   // 1047 used
    __shared__ __align__(16) ull us[KC * 5];       // 240 taps as 120 pairs
    float* usf = reinterpret_cast<float*>(us);

    const int tid = threadIdx.x;
    const int w = tid >> 5, l = tid & 31;
    const int b   = blockIdx.y;
    const int t0  = blockIdx.x * TBc;

    // ---- prologue: 240 warp-dots, 30 per warp ----
    for (int i = 0; i < 30; ++i) {
        int d = w * 30 + i;               // 0..239
        int k = d / OUTD, o = d - k * OUTD;
        const float* L = (k < 8) ? (W3 + o * HH) : (g_Y + o * HH);
        const float* v = (k < 8) ? &g_V[k][0] : &g_V[k - 8][0];
        const float4* L4 = reinterpret_cast<const float4*>(L);
        const float4* V4 = reinterpret_cast<const float4*>(v);
        float4 a = __ldg(L4 + l), c = __ldg(L4 + 32 + l);
        float4 va = __ldg(V4 + l), vb = __ldg(V4 + 32 + l);
        float p = a.x * va.x + a.y * va.y + a.z * va.z + a.w * va.w
                + c.x * vb.x + c.y * vb.y + c.z * vb.z + c.w * vb.w;
#pragma unroll
        for (int off = 16; off; off >>= 1)
            p += __shfl_xor_sync(0xffffffffu, p, off);
        if (l == 0) usf[k * OUTD + o] = p;
    }

    // ---- x tile ----
    const float* xb = x + (size_t)b * TT;
    for (int i = tid; i < TBc + KC - 1; i += 256) {
        int gi = t0 - (KC - 1) + i;
        xs[i] = (gi >= 0) ? __ldg(xb + gi) : 0.f;
    }
    __syncthreads();

    // ---- conv core ----
    ull a[4][5];
#pragma unroll
    for (int j = 0; j < 4; ++j)
#pragma unroll
        for (int p = 0; p < 5; ++p) a[j][p] = 0ull;

#pragma unroll 4
    for (int k = 0; k < KC; ++k) {
        ull u0 = us[k * 5 + 0], u1 = us[k * 5 + 1], u2 = us[k * 5 + 2];
        ull u3 = us[k * 5 + 3], u4 = us[k * 5 + 4];
#pragma unroll
        for (int j = 0; j < 4; ++j) {
            ull xv = pack_dup(xs[tid + j * 256 + (KC - 1) - k]);
            a[j][0] = fma2(xv, u0, a[j][0]);
            a[j][1] = fma2(xv, u1, a[j][1]);
            a[j][2] = fma2(xv, u2, a[j][2]);
            a[j][3] = fma2(xv, u3, a[j][3]);
            a[j][4] = fma2(xv, u4, a[j][4]);
        }
    }

#pragma unroll
    for (int j = 0; j < 4; ++j) {
        int t = t0 + tid + j * 256;
        float2* yp = reinterpret_cast<float2*>(y + ((size_t)b * TT + t) * OUTD);
#pragma unroll
        for (int p = 0; p < 5; ++p) yp[p] = unpack2(a[j][p]);
    }
}

// ---------------------------------------------------------------------------
extern "C" void kernel_launch(void* const* d_in, const int* in_sizes, int n_in,
                              void* d_out, int out_size)
{
    const float *x = nullptr, *W1 = nullptr, *W2 = nullptr, *W3 = nullptr;
    for (int idx = 0; idx < n_in; ++idx) {
        int s = in_sizes[idx];
        const float* p = (const float*)d_in[idx];
        if      (s == BB * TT)   x  = p;
        else if (s == HH)        W1 = p;
        else if (s == HH * HH)   W2 = p;
        else if (s == OUTD * HH) W3 = p;
    }

    cudaFuncSetAttribute(gemm_seed_kernel,
                         cudaFuncAttributeMaxDynamicSharedMemorySize,
                         GEMM_SMEM_BYTES);

    gemm_seed_kernel<<<72, 256, GEMM_SMEM_BYTES>>>(W2, W1, 0); // P2 | v0,v1
    gemm_seed_kernel<<<80, 256, GEMM_SMEM_BYTES>>>(W2, W1, 1); // P4 | v2,v3
    prep_kernel<<<50, 256>>>(W3);                              // v4..15 | Y
    conv_kernel<<<dim3(TT / TBc, BB, 1), 256>>>(x, (float*)d_out, W3);
}

// round 13
// speedup vs baseline: 1.0115x; 1.0115x over previous
#include <cuda_runtime.h>
#include <cstdint>

// CustomRNN: h_t = W2 h_{t-1} + x_t w1 ; y_t = W3 h_t
// => causal conv y[b,t] = sum_k u_k x[b,t-k], u_k = W3 W2^k w1, KC=24.
// 4 graph-captured launches:
//  K1: P2=W2^2        | v0=w1, v1=W2 w1
//  K2: P4=P2^2        | v2,v3 = P2{v0,v1}
//  K3: v4..7=P4{v0..3} | v8..15=P4^2 v_b (2-3 block-local hops) | Y=W3*P4^2
//  K4: conv; prologue computes taps u_k from {W3,Y} x {v0..15}

#define BB   64
#define TT   8192
#define HH   256
#define OUTD 10
#define KC   24
#define TBc  1024
#define GP   260

typedef unsigned long long ull;

// ---- device scratch ----
__device__ __align__(16) float g_P2[HH * HH];
__device__ __align__(16) float g_P4[HH * HH];
__device__ __align__(16) float g_V[16][HH];     // v0..v15
__device__ __align__(16) float g_Y[OUTD * HH];  // Y = W3 * W2^8

// ---- packed f32x2 helpers ----
__device__ __forceinline__ ull fma2(ull a, ull b, ull c) {
    ull d;
    asm("fma.rn.f32x2 %0, %1, %2, %3;" : "=l"(d) : "l"(a), "l"(b), "l"(c));
    return d;
}
__device__ __forceinline__ ull pack_dup(float x) {
    ull d; unsigned u = __float_as_uint(x);
    asm("mov.b64 %0, {%1, %1};" : "=l"(d) : "r"(u));
    return d;
}
__device__ __forceinline__ float2 unpack2(ull a) {
    float2 f;
    asm("mov.b64 {%0, %1}, %2;" : "=f"(f.x), "=f"(f.y) : "l"(a));
    return f;
}

// ---- 32x32-tile GEMM square: C = X @ X (blocks 0..63) ----
__device__ void gemm_tile(const float* __restrict__ X, float* C, int bid,
                          float* sm)
{
    float* Xr = sm;                // [32][GP]
    float* Xc = sm + 32 * GP;      // [256][32]
    const int tid = threadIdx.x;
    const int i0 = (bid >> 3) * 32;
    const int j0 = (bid & 7) * 32;

    for (int n = tid; n < 32 * 256; n += 256) {
        int rr = n >> 8, kk = n & 255;
        Xr[rr * GP + kk] = __ldg(X + (i0 + rr) * HH + kk);
    }
    for (int n = tid; n < 256 * 32; n += 256) {
        int kk = n >> 5, jj = n & 31;
        Xc[kk * 32 + jj] = __ldg(X + kk * HH + j0 + jj);
    }
    __syncthreads();

    const int r0 = (tid >> 4) * 2;
    const int c0 = (tid & 15) * 2;
    ull q0 = 0ull, q1 = 0ull;
#pragma unroll 8
    for (int k = 0; k < 256; ++k) {
        ull cp = *reinterpret_cast<const ull*>(&Xc[k * 32 + c0]);
        ull a0 = pack_dup(Xr[r0 * GP + k]);
        ull a1 = pack_dup(Xr[(r0 + 1) * GP + k]);
        q0 = fma2(a0, cp, q0);
        q1 = fma2(a1, cp, q1);
    }
    float2 f0 = unpack2(q0), f1 = unpack2(q1);
    *reinterpret_cast<float2*>(&C[(i0 + r0) * HH + j0 + c0]) = f0;
    *reinterpret_cast<float2*>(&C[(i0 + r0 + 1) * HH + j0 + c0]) = f1;
}

// ---- 32-row matvec slice with prefetch: vout[row0..row0+31] = M @ vin ----
__device__ void matvec32(const float* __restrict__ M,
                         const float* __restrict__ vin,
                         float* __restrict__ vout, int row0)
{
    const int w = threadIdx.x >> 5, l = threadIdx.x & 31;
    const float4* vp = reinterpret_cast<const float4*>(vin);
    float4 va = __ldg(vp + l);
    float4 vb = __ldg(vp + 32 + l);
    float4 ma[4], mb[4];
#pragma unroll
    for (int rr = 0; rr < 4; ++rr) {
        const float4* mp =
            reinterpret_cast<const float4*>(M + (row0 + w + rr * 8) * HH);
        ma[rr] = __ldg(mp + l);
        mb[rr] = __ldg(mp + 32 + l);
    }
    float p[4];
#pragma unroll
    for (int rr = 0; rr < 4; ++rr)
        p[rr] = ma[rr].x * va.x + ma[rr].y * va.y + ma[rr].z * va.z + ma[rr].w * va.w
              + mb[rr].x * vb.x + mb[rr].y * vb.y + mb[rr].z * vb.z + mb[rr].w * vb.w;
#pragma unroll
    for (int off = 16; off; off >>= 1)
#pragma unroll
        for (int rr = 0; rr < 4; ++rr)
            p[rr] += __shfl_xor_sync(0xffffffffu, p[rr], off);
    if (l == 0) {
#pragma unroll
        for (int rr = 0; rr < 4; ++rr) vout[row0 + w + rr * 8] = p[rr];
    }
}

// ---- block-local chained matvec: vdst = M^hops @ vsrc (one block) ----
__device__ void chain_matvec(const float* __restrict__ M,
                             const float* __restrict__ vsrc,
                             float* __restrict__ vdst, int hops)
{
    __shared__ float buf[2][HH];
    const int tid = threadIdx.x, w = tid >> 5, l = tid & 31;
    buf[0][tid] = __ldg(vsrc + tid);
    __syncthreads();
    int cur = 0;
    for (int h = 0; h < hops; ++h) {
        const float4* v4 = reinterpret_cast<const float4*>(buf[cur]);
        float4 va = v4[l], vb = v4[32 + l];
        float* outp = (h == hops - 1) ? vdst : buf[cur ^ 1];
        for (int ib = 0; ib < 8; ++ib) {
            float4 ma[4], mb[4];
#pragma unroll
            for (int rr = 0; rr < 4; ++rr) {
                const float4* mp = reinterpret_cast<const float4*>(
                    M + (w * 32 + ib * 4 + rr) * HH);
                ma[rr] = __ldg(mp + l);
                mb[rr] = __ldg(mp + 32 + l);
            }
            float p[4];
#pragma unroll
            for (int rr = 0; rr < 4; ++rr)
                p[rr] = ma[rr].x * va.x + ma[rr].y * va.y + ma[rr].z * va.z + ma[rr].w * va.w
                      + mb[rr].x * vb.x + mb[rr].y * vb.y + mb[rr].z * vb.z + mb[rr].w * vb.w;
#pragma unroll
            for (int off = 16; off; off >>= 1)
#pragma unroll
                for (int rr = 0; rr < 4; ++rr)
                    p[rr] += __shfl_xor_sync(0xffffffffu, p[rr], off);
            if (l == 0) {
#pragma unroll
                for (int rr = 0; rr < 4; ++rr) outp[w * 32 + ib * 4 + rr] = p[rr];
            }
        }
        __syncthreads();
        cur ^= 1;
    }
}

// ---- Y row: g_Y[o] = W3[o] @ P4 @ P4 (two in-block vec-mat passes) ----
__device__ void y_row(const float* __restrict__ W3, int o)
{
    __shared__ float r0[HH], r1[HH];
    const int tid = threadIdx.x;
    r0[tid] = __ldg(W3 + o * HH + tid);
    __syncthreads();
    float acc = 0.f;
#pragma unroll 8
    for (int k = 0; k < HH; ++k)
        acc = fmaf(r0[k], __ldg(g_P4 + k * HH + tid), acc);
    r1[tid] = acc;
    __syncthreads();
    acc = 0.f;
#pragma unroll 8
    for (int k = 0; k < HH; ++k)
        acc = fmaf(r1[k], __ldg(g_P4 + k * HH + tid), acc);
    g_Y[o * HH + tid] = acc;
}

// ---- K1/K2: GEMM square + seed matvecs ----
#define GEMM_SMEM_BYTES ((32 * GP + 256 * 32) * 4)

extern "C" __global__ void __launch_bounds__(256, 2)
gemm_seed_kernel(const float* __restrict__ W2,
                 const float* __restrict__ W1, int phase)
{
    extern __shared__ float sm[];
    const int bid = blockIdx.x;
    const float* X = (phase == 0) ? W2 : g_P2;
    float*       C = (phase == 0) ? g_P2 : g_P4;

    if (bid < 64) {
        gemm_tile(X, C, bid, sm);
    } else if (phase == 0) {
        if (bid == 64) g_V[0][threadIdx.x] = __ldg(W1 + threadIdx.x);
        matvec32(W2, W1, &g_V[1][0], (bid - 64) * 32);
    } else {
        int s = (bid - 64) >> 3;
        matvec32(g_P2, &g_V[s][0], &g_V[2 + s][0], ((bid - 64) & 7) * 32);
    }
}

// ---- K3: v4..7 slices | v8..15 chained | Y rows  (grid 50) ----
extern "C" __global__ void __launch_bounds__(256)
prep_kernel(const float* __restrict__ W3)
{
    const int bid = blockIdx.x;
    if (bid < 32) {
        int s = bid >> 3;
        matvec32(g_P4, &g_V[s][0], &g_V[4 + s][0], (bid & 7) * 32);
    } else if (bid < 40) {
        int j = bid - 32;                 // v_{8+j} = P4^2 v_j
        int hops = (j < 4) ? 2 : 3;       // j>=4: P4^3 v_{j-4}
        int src  = (j < 4) ? j : j - 4;
        chain_matvec(g_P4, &g_V[src][0], &g_V[8 + j][0], hops);
    } else {
        y_row(W3, bid - 40);
    }
}

// ---- K4: conv. grid (8, 64) x 256 threads, 4 t/thread, tap prologue ----
extern "C" __global__ void __launch_bounds__(256)
conv_kernel(const float* __restrict__ x, float* __restrict__ y,
            const float* __restrict__ W3)
{
    __shared__ __align__(16) float xs[TBc + KC];   // 1047 used
    __shared__ __align__(16) ull us[KC * 5];       // 240 taps as 120 pairs
    float* usf = reinterpret_cast<float*>(us);

    const int tid = threadIdx.x;
    const int w = tid >> 5, l = tid & 31;
    const int b   = blockIdx.y;
    const int t0  = blockIdx.x * TBc;

    // ---- prologue: 240 warp-dots, 30 per warp ----
    for (int i = 0; i < 30; ++i) {
        int d = w * 30 + i;               // 0..239
        int k = d / OUTD, o = d - k * OUTD;
        const float* L = (k < 8) ? (W3 + o * HH) : (g_Y + o * HH);
        const float* v = (k < 8) ? &g_V[k][0] : &g_V[k - 8][0];
        const float4* L4 = reinterpret_cast<const float4*>(L);
        const float4* V4 = reinterpret_cast<const float4*>(v);
        float4 a = __ldg(L4 + l), c = __ldg(L4 + 32 + l);
        float4 va = __ldg(V4 + l), vb = __ldg(V4 + 32 + l);
        float p = a.x * va.x + a.y * va.y + a.z * va.z + a.w * va.w
                + c.x * vb.x + c.y * vb.y + c.z * vb.z + c.w * vb.w;
#pragma unroll
        for (int off = 16; off; off >>= 1)
            p += __shfl_xor_sync(0xffffffffu, p, off);
        if (l == 0) usf[k * OUTD + o] = p;
    }

    // ---- x tile ----
    const float* xb = x + (size_t)b * TT;
    for (int i = tid; i < TBc + KC - 1; i += 256) {
        int gi = t0 - (KC - 1) + i;
        xs[i] = (gi >= 0) ? __ldg(xb + gi) : 0.f;
    }
    __syncthreads();

    // ---- conv core ----
    ull a[4][5];
#pragma unroll
    for (int j = 0; j < 4; ++j)
#pragma unroll
        for (int p = 0; p < 5; ++p) a[j][p] = 0ull;

#pragma unroll 4
    for (int k = 0; k < KC; ++k) {
        ull u0 = us[k * 5 + 0], u1 = us[k * 5 + 1], u2 = us[k * 5 + 2];
        ull u3 = us[k * 5 + 3], u4 = us[k * 5 + 4];
#pragma unroll
        for (int j = 0; j < 4; ++j) {
            ull xv = pack_dup(xs[tid + j * 256 + (KC - 1) - k]);
            a[j][0] = fma2(xv, u0, a[j][0]);
            a[j][1] = fma2(xv, u1, a[j][1]);
            a[j][2] = fma2(xv, u2, a[j][2]);
            a[j][3] = fma2(xv, u3, a[j][3]);
            a[j][4] = fma2(xv, u4, a[j][4]);
        }
    }

#pragma unroll
    for (int j = 0; j < 4; ++j) {
        int t = t0 + tid + j * 256;
        float2* yp = reinterpret_cast<float2*>(y + ((size_t)b * TT + t) * OUTD);
#pragma unroll
        for (int p = 0; p < 5; ++p) yp[p] = unpack2(a[j][p]);
    }
}

// ---------------------------------------------------------------------------
extern "C" void kernel_launch(void* const* d_in, const int* in_sizes, int n_in,
                              void* d_out, int out_size)
{
    const float *x = nullptr, *W1 = nullptr, *W2 = nullptr, *W3 = nullptr;
    for (int idx = 0; idx < n_in; ++idx) {
        int s = in_sizes[idx];
        const float* p = (const float*)d_in[idx];
        if      (s == BB * TT)   x  = p;
        else if (s == HH)        W1 = p;
        else if (s == HH * HH)   W2 = p;
        else if (s == OUTD * HH) W3 = p;
    }

    cudaFuncSetAttribute(gemm_seed_kernel,
                         cudaFuncAttributeMaxDynamicSharedMemorySize,
                         GEMM_SMEM_BYTES);

    gemm_seed_kernel<<<72, 256, GEMM_SMEM_BYTES>>>(W2, W1, 0); // P2 | v0,v1
    gemm_seed_kernel<<<80, 256, GEMM_SMEM_BYTES>>>(W2, W1, 1); // P4 | v2,v3
    prep_kernel<<<50, 256>>>(W3);                              // v4..15 | Y
    conv_kernel<<<dim3(TT / TBc, BB, 1), 256>>>(x, (float*)d_out, W3);
}